// round 10
// baseline (speedup 1.0000x reference)
#include <cuda_runtime.h>
#include <cuda_bf16.h>

// Elementwise: y = (x + 1) * 2 / 3; if (y > 0) y -= 5;
// 8192*8192 fp32 = 67,108,864 elements (2^24 float4s). HBM-streaming.
//
// R9: CTA-count gradient: 16384 CTAs=82.69us, 8192=82.43, 4096=82.24.
// This round: 2048 CTAs x 1024 threads, 8 float4/thread, front-batched
// __ldcg loads, default stores. Wallclock floor = 512MB / ~6.2 TB/s.

__device__ __forceinline__ float4 transform4(float4 v) {
    const float c = 2.0f / 3.0f;   // (x+1)*2/3 == fma(x, 2/3, 2/3)
    float4 r;
    r.x = fmaf(v.x, c, c);
    r.y = fmaf(v.y, c, c);
    r.z = fmaf(v.z, c, c);
    r.w = fmaf(v.w, c, c);
    if (r.x > 0.0f) r.x -= 5.0f;
    if (r.y > 0.0f) r.y -= 5.0f;
    if (r.z > 0.0f) r.z -= 5.0f;
    if (r.w > 0.0f) r.w -= 5.0f;
    return r;
}

// Each block: 1024 threads * 8 float4 = 8192 float4s. No bounds checks;
// launcher guarantees exact divisibility on the fast path.
__global__ __launch_bounds__(1024) void ew_flat8_b1024(const float4* __restrict__ x,
                                                       float4* __restrict__ out) {
    int base = blockIdx.x * (1024 * 8) + threadIdx.x;

    float4 v0 = __ldcg(x + base + 0 * 1024);
    float4 v1 = __ldcg(x + base + 1 * 1024);
    float4 v2 = __ldcg(x + base + 2 * 1024);
    float4 v3 = __ldcg(x + base + 3 * 1024);
    out[base + 0 * 1024] = transform4(v0);
    out[base + 1 * 1024] = transform4(v1);
    out[base + 2 * 1024] = transform4(v2);
    out[base + 3 * 1024] = transform4(v3);

    float4 v4 = __ldcg(x + base + 4 * 1024);
    float4 v5 = __ldcg(x + base + 5 * 1024);
    float4 v6 = __ldcg(x + base + 6 * 1024);
    float4 v7 = __ldcg(x + base + 7 * 1024);
    out[base + 4 * 1024] = transform4(v4);
    out[base + 5 * 1024] = transform4(v5);
    out[base + 6 * 1024] = transform4(v6);
    out[base + 7 * 1024] = transform4(v7);
}

// Fallback grid-stride for arbitrary sizes.
__global__ __launch_bounds__(256) void ew_gs(const float4* __restrict__ x,
                                             float4* __restrict__ out, int n4) {
    int i = blockIdx.x * blockDim.x + threadIdx.x;
    int stride = gridDim.x * blockDim.x;
    for (; i < n4; i += stride)
        out[i] = transform4(__ldcg(x + i));
}

__global__ void ew_scalar_tail(const float* __restrict__ x,
                               float* __restrict__ out, int start, int n) {
    int i = start + blockIdx.x * blockDim.x + threadIdx.x;
    if (i < n) {
        const float c = 2.0f / 3.0f;
        float r = fmaf(x[i], c, c);
        if (r > 0.0f) r -= 5.0f;
        out[i] = r;
    }
}

extern "C" void kernel_launch(void* const* d_in, const int* in_sizes, int n_in,
                              void* d_out, int out_size) {
    const float* x = (const float*)d_in[0];
    float* out = (float*)d_out;
    int n = in_sizes[0];          // 67,108,864
    int n4 = n >> 2;              // 16,777,216 = 2^24

    const int per_block = 1024 * 8;  // 8192 float4s per block
    if ((n % 4) == 0 && (n4 % per_block) == 0) {
        int blocks = n4 / per_block;  // 2048
        ew_flat8_b1024<<<blocks, 1024>>>((const float4*)x, (float4*)out);
    } else {
        int n4f = n >> 2;
        if (n4f > 0) {
            int b = (n4f + 256 * 8 - 1) / (256 * 8);
            ew_gs<<<b, 256>>>((const float4*)x, (float4*)out, n4f);
        }
        int tail = n - (n4f << 2);
        if (tail > 0)
            ew_scalar_tail<<<(tail + 255) / 256, 256>>>(x, out, n4f << 2, n);
    }
}